// round 2
// baseline (speedup 1.0000x reference)
#include <cuda_runtime.h>
#include <cuda_bf16.h>

// One warp per batch element. 8-qubit state (256 complex amps) held in
// registers: lane = amp>>3 (qubits 0..4 in lane bits 4..0), reg r = amp&7
// (qubits 5..7 in bits 2..0). Gate matrices precomputed by prep kernel.

#define NQ 8
#define FULLMASK 0xffffffffu

__device__ float g_gates[3 * 16 * 8];   // [branch][gate][8 floats: u00r,u00i,u01r,u01i,u10r,u10i,u11r,u11i]

__global__ void prep_gates(const float* __restrict__ crx, const float* __restrict__ u3x,
                           const float* __restrict__ cry, const float* __restrict__ u3y,
                           const float* __restrict__ crz, const float* __restrict__ u3z) {
    int i = threadIdx.x;
    if (i >= 48) return;
    int br = i >> 4;
    int gi = i & 15;
    const float* crp = (br == 0) ? crx : (br == 1) ? cry : crz;
    const float* u3p = (br == 0) ? u3x : (br == 1) ? u3y : u3z;
    float m[8];
    if (gi < 10) {
        float t = 0.5f * crp[gi];
        float c = cosf(t), s = sinf(t);
        if (br == 0) {            // RX: [[c, -i s],[-i s, c]]
            m[0] = c;  m[1] = 0.f; m[2] = 0.f; m[3] = -s;
            m[4] = 0.f; m[5] = -s; m[6] = c;  m[7] = 0.f;
        } else if (br == 1) {     // RY: [[c, -s],[s, c]]
            m[0] = c;  m[1] = 0.f; m[2] = -s; m[3] = 0.f;
            m[4] = s;  m[5] = 0.f; m[6] = c;  m[7] = 0.f;
        } else {                  // RZ: diag(e^{-it/2}, e^{+it/2})
            m[0] = c;  m[1] = -s;  m[2] = 0.f; m[3] = 0.f;
            m[4] = 0.f; m[5] = 0.f; m[6] = c;  m[7] = s;
        }
    } else {
        int u = gi - 10;
        float th = u3p[3 * u], ph = u3p[3 * u + 1], lm = u3p[3 * u + 2];
        float ct = cosf(0.5f * th), st = sinf(0.5f * th);
        float cp = cosf(ph), sp = sinf(ph);
        float cl = cosf(lm), sl = sinf(lm);
        m[0] = ct;        m[1] = 0.f;
        m[2] = -cl * st;  m[3] = -sl * st;
        m[4] = cp * st;   m[5] = sp * st;
        float cpl = cp * cl - sp * sl;
        float spl = sp * cl + cp * sl;
        m[6] = cpl * ct;  m[7] = spl * ct;
    }
#pragma unroll
    for (int k = 0; k < 8; k++) g_gates[i * 8 + k] = m[k];
}

// Gate with target qubit resident in lane bits. tbit = lane bit of target.
// act: per-lane predicate (control bit); shfls are unconditional.
__device__ __forceinline__ void gate_lane(float sr[8], float si[8],
                                          const float* __restrict__ g,
                                          int tbit, bool act) {
    const unsigned m = 1u << tbit;
    const int bit = (threadIdx.x >> tbit) & 1;
    const float cmr = bit ? g[6] : g[0];
    const float cmi = bit ? g[7] : g[1];
    const float cpr = bit ? g[4] : g[2];
    const float cpi = bit ? g[5] : g[3];
#pragma unroll
    for (int r = 0; r < 8; r++) {
        float pr = __shfl_xor_sync(FULLMASK, sr[r], m);
        float pi = __shfl_xor_sync(FULLMASK, si[r], m);
        float nr = cmr * sr[r] - cmi * si[r] + cpr * pr - cpi * pi;
        float ni = cmr * si[r] + cmi * sr[r] + cpr * pi + cpi * pr;
        if (act) { sr[r] = nr; si[r] = ni; }
    }
}

// Gate with target qubit resident in register bits. TB = register bit of
// target. MASK: compile-time mask of active low-pair indices r0 (encodes a
// register-resident control). lane_act: runtime lane-resident control.
template <int TB, unsigned MASK>
__device__ __forceinline__ void gate_reg(float sr[8], float si[8],
                                         const float* __restrict__ g,
                                         bool lane_act) {
    const float u00r = g[0], u00i = g[1], u01r = g[2], u01i = g[3];
    const float u10r = g[4], u10i = g[5], u11r = g[6], u11i = g[7];
#pragma unroll
    for (int r0 = 0; r0 < 8; r0++) {
        if (r0 & (1 << TB)) continue;
        if (!((MASK >> r0) & 1)) continue;
        const int r1 = r0 | (1 << TB);
        float ar = sr[r0], ai = si[r0];
        float br_ = sr[r1], bi = si[r1];
        float n0r = u00r * ar - u00i * ai + u01r * br_ - u01i * bi;
        float n0i = u00r * ai + u00i * ar + u01r * bi + u01i * br_;
        float n1r = u10r * ar - u10i * ai + u11r * br_ - u11i * bi;
        float n1i = u10r * ai + u10i * ar + u11r * bi + u11i * br_;
        if (lane_act) {
            sr[r0] = n0r; si[r0] = n0i;
            sr[r1] = n1r; si[r1] = n1i;
        }
    }
}

__global__ __launch_bounds__(256) void qcnn_main(
    const float* __restrict__ x,
    const float* __restrict__ w1, const float* __restrict__ b1,
    const float* __restrict__ w2, const float* __restrict__ b2,
    float* __restrict__ out, int B) {
    __shared__ float sg[384];
    __shared__ float sw1[72];
    __shared__ float sb1[12];
    __shared__ float sw2[12];
    __shared__ float sb2;

    int t = threadIdx.x;
    // FIX (R1 bug): blockDim is 256 but sg has 384 entries — strided load so
    // branch-2 (RZ) gate matrices are actually populated.
    for (int i = t; i < 384; i += 256) sg[i] = g_gates[i];
    if (t < 72) sw1[t] = w1[t];
    if (t >= 72 && t < 84) sb1[t - 72] = b1[t - 72];
    if (t >= 84 && t < 96) sw2[t - 84] = w2[t - 84];
    if (t == 96) sb2 = b2[0];
    __syncthreads();

    int warp = (blockIdx.x * blockDim.x + t) >> 5;
    if (warp >= B) return;
    int lane = t & 31;

    // ---- encode: product state from cos/sin(x/2) ----
    float xv = x[(warp << 3) + (lane & 7)];
    float ch = __cosf(0.5f * xv);
    float sh = __sinf(0.5f * xv);
    float c0 = __shfl_sync(FULLMASK, ch, 0), s0 = __shfl_sync(FULLMASK, sh, 0);
    float c1 = __shfl_sync(FULLMASK, ch, 1), s1 = __shfl_sync(FULLMASK, sh, 1);
    float c2 = __shfl_sync(FULLMASK, ch, 2), s2 = __shfl_sync(FULLMASK, sh, 2);
    float c3 = __shfl_sync(FULLMASK, ch, 3), s3 = __shfl_sync(FULLMASK, sh, 3);
    float c4 = __shfl_sync(FULLMASK, ch, 4), s4 = __shfl_sync(FULLMASK, sh, 4);
    float c5 = __shfl_sync(FULLMASK, ch, 5), s5 = __shfl_sync(FULLMASK, sh, 5);
    float c6 = __shfl_sync(FULLMASK, ch, 6), s6 = __shfl_sync(FULLMASK, sh, 6);
    float c7 = __shfl_sync(FULLMASK, ch, 7), s7 = __shfl_sync(FULLMASK, sh, 7);

    float L = (((lane >> 4) & 1) ? s0 : c0)
            * (((lane >> 3) & 1) ? s1 : c1)
            * (((lane >> 2) & 1) ? s2 : c2)
            * (((lane >> 1) & 1) ? s3 : c3)
            * ((lane & 1) ? s4 : c4);

    float init[8];
#pragma unroll
    for (int r = 0; r < 8; r++)
        init[r] = L * ((r & 4) ? s5 : c5) * ((r & 2) ? s6 : c6) * ((r & 1) ? s7 : c7);

    float f0, f1, f2, f3, f4, f5v;

#pragma unroll 1
    for (int br = 0; br < 3; br++) {
        const float* G = sg + br * 128;
        float sr[8], si[8];
#pragma unroll
        for (int r = 0; r < 8; r++) { sr[r] = init[r]; si[r] = 0.f; }

        // CR_PAIRS_1 (qubit q -> lane bit 4-q for q<=4, reg bit 7-q for q>=5)
        gate_lane(sr, si, G + 0,  3, ((lane >> 4) & 1) != 0);     // (0,1)
        gate_lane(sr, si, G + 8,  1, ((lane >> 2) & 1) != 0);     // (2,3)
        gate_reg<2, 0x0F>(sr, si, G + 16, (lane & 1) != 0);       // (4,5)
        gate_reg<0, 0x44>(sr, si, G + 24, true);                  // (6,7) ctrl reg bit1
        gate_lane(sr, si, G + 32, 2, ((lane >> 3) & 1) != 0);     // (1,2)
        gate_lane(sr, si, G + 40, 0, ((lane >> 1) & 1) != 0);     // (3,4)
        gate_reg<1, 0x30>(sr, si, G + 48, true);                  // (5,6) ctrl reg bit2

        // U3 on wires 1,3,5,7
        gate_lane(sr, si, G + 80, 3, true);                       // u3[0] wire1
        gate_lane(sr, si, G + 88, 1, true);                       // u3[1] wire3
        gate_reg<2, 0x0F>(sr, si, G + 96, true);                  // u3[2] wire5
        gate_reg<0, 0x55>(sr, si, G + 104, true);                 // u3[3] wire7

        // CR_PAIRS_2
        gate_lane(sr, si, G + 56, 1, ((lane >> 3) & 1) != 0);     // (1,3)
        gate_reg<0, 0x50>(sr, si, G + 64, true);                  // (5,7) ctrl reg bit2
        gate_reg<2, 0x0F>(sr, si, G + 72, ((lane >> 1) & 1) != 0);// (3,5)

        // Final U3
        gate_lane(sr, si, G + 112, 1, true);                      // u3[4] wire3
        gate_reg<0, 0x55>(sr, si, G + 120, true);                 // u3[5] wire7

        // expval_z on qubit 3 (lane bit 1) and qubit 7 (reg bit 0)
        float e3 = 0.f, e7 = 0.f;
        float sgn3 = ((lane >> 1) & 1) ? -1.f : 1.f;
#pragma unroll
        for (int r = 0; r < 8; r++) {
            float p = sr[r] * sr[r] + si[r] * si[r];
            e3 += sgn3 * p;
            e7 += (r & 1) ? -p : p;
        }
#pragma unroll
        for (int o = 16; o; o >>= 1) {
            e3 += __shfl_xor_sync(FULLMASK, e3, o);
            e7 += __shfl_xor_sync(FULLMASK, e7, o);
        }

        if (br == 0)      { f0 = e3; f1 = e7; }
        else if (br == 1) { f2 = e3; f3 = e7; }
        else              { f4 = e3; f5v = e7; }
    }

    // ---- MLP head on lane 0 ----
    if (lane == 0) {
        float z = sb2;
#pragma unroll
        for (int j = 0; j < 12; j++) {
            float h = sb1[j]
                    + sw1[j * 6 + 0] * f0 + sw1[j * 6 + 1] * f1
                    + sw1[j * 6 + 2] * f2 + sw1[j * 6 + 3] * f3
                    + sw1[j * 6 + 4] * f4 + sw1[j * 6 + 5] * f5v;
            z += sw2[j] * tanhf(h);
        }
        out[warp] = 1.0f / (1.0f + expf(-z));
    }
}

extern "C" void kernel_launch(void* const* d_in, const int* in_sizes, int n_in,
                              void* d_out, int out_size) {
    const float* x    = (const float*)d_in[0];
    const float* crx  = (const float*)d_in[1];
    const float* u3x  = (const float*)d_in[2];
    const float* cry  = (const float*)d_in[3];
    const float* u3y  = (const float*)d_in[4];
    const float* crz  = (const float*)d_in[5];
    const float* u3z  = (const float*)d_in[6];
    const float* w1   = (const float*)d_in[7];
    const float* b1   = (const float*)d_in[8];
    const float* w2   = (const float*)d_in[9];
    const float* b2   = (const float*)d_in[10];
    float* out = (float*)d_out;

    int B = in_sizes[0] / NQ;   // 32768

    prep_gates<<<1, 64>>>(crx, u3x, cry, u3y, crz, u3z);

    int threads = 256;
    int warps_per_block = threads / 32;
    int blocks = (B + warps_per_block - 1) / warps_per_block;
    qcnn_main<<<blocks, threads>>>(x, w1, b1, w2, b2, out, B);
}

// round 3
// speedup vs baseline: 1.5703x; 1.5703x over previous
#include <cuda_runtime.h>
#include <cuda_bf16.h>

// One warp per batch element. 8-qubit state (256 complex amps) in registers:
// lane = amp>>3 (qubits 0..4 in lane bits 4..0), reg r = amp&7 (qubits 5..7).
// Specialized per-branch gate math: CRX/CRY use 4-FFMA updates; CRZ layers
// collapse into precomputed per-amplitude phase tables (diagonal compose).

#define NQ 8
#define FULLMASK 0xffffffffu

__device__ float  g_cr[60];       // [br][10][{c,s}]
__device__ float  g_u3[144];      // [br][6][8]
__device__ float2 g_zt[2][256];   // [layer][(a&7)*32 + (a>>3)] = e^{i phi}

__global__ void prep_gates(const float* __restrict__ crx, const float* __restrict__ u3x,
                           const float* __restrict__ cry, const float* __restrict__ u3y,
                           const float* __restrict__ crz, const float* __restrict__ u3z) {
    int t = threadIdx.x;
    if (t < 30) {
        int br = t / 10, g = t % 10;
        const float* crp = (br == 0) ? crx : (br == 1) ? cry : crz;
        float th = 0.5f * crp[g];
        g_cr[(br * 10 + g) * 2 + 0] = cosf(th);
        g_cr[(br * 10 + g) * 2 + 1] = sinf(th);
    }
    if (t >= 32 && t < 50) {
        int i = t - 32;
        int br = i / 6, u = i % 6;
        const float* u3p = (br == 0) ? u3x : (br == 1) ? u3y : u3z;
        float th = u3p[3 * u], ph = u3p[3 * u + 1], lm = u3p[3 * u + 2];
        float ct = cosf(0.5f * th), st = sinf(0.5f * th);
        float cp = cosf(ph), sp = sinf(ph);
        float cl = cosf(lm), sl = sinf(lm);
        float* m = &g_u3[(br * 6 + u) * 8];
        m[0] = ct;        m[1] = 0.f;
        m[2] = -cl * st;  m[3] = -sl * st;
        m[4] = cp * st;   m[5] = sp * st;
        m[6] = (cp * cl - sp * sl) * ct;
        m[7] = (sp * cl + cp * sl) * ct;
    }
    // CRZ phase tables: amp a = t. bit(a,q) = (a >> (7-q)) & 1.
    {
        int a = t;
        const int c1[7] = {0, 2, 4, 6, 1, 3, 5};
        const int t1[7] = {1, 3, 5, 7, 2, 4, 6};
        const int c2[3] = {1, 5, 3};
        const int t2[3] = {3, 7, 5};
        float p1 = 0.f, p2 = 0.f;
        for (int i = 0; i < 7; i++)
            if ((a >> (7 - c1[i])) & 1)
                p1 += ((a >> (7 - t1[i])) & 1) ? 0.5f * crz[i] : -0.5f * crz[i];
        for (int i = 0; i < 3; i++)
            if ((a >> (7 - c2[i])) & 1)
                p2 += ((a >> (7 - t2[i])) & 1) ? 0.5f * crz[7 + i] : -0.5f * crz[7 + i];
        int idx = (a & 7) * 32 + (a >> 3);   // transposed for conflict-free LDS.64
        g_zt[0][idx] = make_float2(cosf(p1), sinf(p1));
        g_zt[1][idx] = make_float2(cosf(p2), sinf(p2));
    }
}

// ---- specialized CR gates (BR: 0=X, 1=Y) ----
template <int BR>
__device__ __forceinline__ void cr_lane(float (&sr)[8], float (&si)[8],
                                        float c, float s, int tbit, bool act, int lane) {
    const unsigned m = 1u << tbit;
    float coef = s;
    if (BR == 1) coef = ((lane >> tbit) & 1) ? s : -s;
#pragma unroll
    for (int r = 0; r < 8; r++) {
        float pr = __shfl_xor_sync(FULLMASK, sr[r], m);
        float pi = __shfl_xor_sync(FULLMASK, si[r], m);
        float nr, ni;
        if (BR == 0) { nr = fmaf(coef, pi, c * sr[r]); ni = fmaf(-coef, pr, c * si[r]); }
        else         { nr = fmaf(coef, pr, c * sr[r]); ni = fmaf(coef, pi, c * si[r]); }
        if (act) { sr[r] = nr; si[r] = ni; }
    }
}

template <int BR, int TB, unsigned MASK>
__device__ __forceinline__ void cr_reg(float (&sr)[8], float (&si)[8],
                                       float c, float s, bool act) {
#pragma unroll
    for (int r0 = 0; r0 < 8; r0++) {
        if (r0 & (1 << TB)) continue;
        if (!((MASK >> r0) & 1)) continue;
        const int r1 = r0 | (1 << TB);
        float ar = sr[r0], ai = si[r0];
        float br_ = sr[r1], bi = si[r1];
        float n0r, n0i, n1r, n1i;
        if (BR == 0) {
            n0r = fmaf(s, bi, c * ar);   n0i = fmaf(-s, br_, c * ai);
            n1r = fmaf(s, ai, c * br_);  n1i = fmaf(-s, ar, c * bi);
        } else {
            n0r = fmaf(-s, br_, c * ar); n0i = fmaf(-s, bi, c * ai);
            n1r = fmaf(s, ar, c * br_);  n1i = fmaf(s, ai, c * bi);
        }
        if (act) { sr[r0] = n0r; si[r0] = n0i; sr[r1] = n1r; si[r1] = n1i; }
    }
}

// CRZ layer: per-amplitude phase multiply from smem table (transposed layout)
__device__ __forceinline__ void ztab_apply(float (&sr)[8], float (&si)[8],
                                           const float2* __restrict__ tab, int lane) {
#pragma unroll
    for (int r = 0; r < 8; r++) {
        float2 p = tab[r * 32 + lane];
        float nr = fmaf(-p.y, si[r], p.x * sr[r]);
        float ni = fmaf(p.y, sr[r], p.x * si[r]);
        sr[r] = nr; si[r] = ni;
    }
}

// ---- generic U3 gates (unconditional) ----
__device__ __forceinline__ void u3_lane(float (&sr)[8], float (&si)[8],
                                        const float* __restrict__ g, int tbit, int lane) {
    const unsigned m = 1u << tbit;
    const int bit = (lane >> tbit) & 1;
    const float cmr = bit ? g[6] : g[0];
    const float cmi = bit ? g[7] : g[1];
    const float cpr = bit ? g[4] : g[2];
    const float cpi = bit ? g[5] : g[3];
#pragma unroll
    for (int r = 0; r < 8; r++) {
        float pr = __shfl_xor_sync(FULLMASK, sr[r], m);
        float pi = __shfl_xor_sync(FULLMASK, si[r], m);
        float nr = cmr * sr[r] - cmi * si[r] + cpr * pr - cpi * pi;
        float ni = cmr * si[r] + cmi * sr[r] + cpr * pi + cpi * pr;
        sr[r] = nr; si[r] = ni;
    }
}

template <int TB, unsigned MASK>
__device__ __forceinline__ void u3_reg(float (&sr)[8], float (&si)[8],
                                       const float* __restrict__ g) {
    const float u00r = g[0], u00i = g[1], u01r = g[2], u01i = g[3];
    const float u10r = g[4], u10i = g[5], u11r = g[6], u11i = g[7];
#pragma unroll
    for (int r0 = 0; r0 < 8; r0++) {
        if (r0 & (1 << TB)) continue;
        if (!((MASK >> r0) & 1)) continue;
        const int r1 = r0 | (1 << TB);
        float ar = sr[r0], ai = si[r0];
        float br_ = sr[r1], bi = si[r1];
        sr[r0] = u00r * ar - u00i * ai + u01r * br_ - u01i * bi;
        si[r0] = u00r * ai + u00i * ar + u01r * bi + u01i * br_;
        sr[r1] = u10r * ar - u10i * ai + u11r * br_ - u11i * bi;
        si[r1] = u10r * ai + u10i * ar + u11r * bi + u11i * br_;
    }
}

template <int BR>
__device__ __forceinline__ void run_branch(const float (&init)[8], int lane,
                                           const float* __restrict__ cr,
                                           const float* __restrict__ u3,
                                           const float2* __restrict__ zt0,
                                           const float2* __restrict__ zt1,
                                           float& e3o, float& e7o) {
    float sr[8], si[8];
#pragma unroll
    for (int r = 0; r < 8; r++) { sr[r] = init[r]; si[r] = 0.f; }

    if (BR < 2) {
        cr_lane<BR>(sr, si, cr[0],  cr[1],  3, ((lane >> 4) & 1) != 0, lane);  // (0,1)
        cr_lane<BR>(sr, si, cr[2],  cr[3],  1, ((lane >> 2) & 1) != 0, lane);  // (2,3)
        cr_reg<BR, 2, 0x0F>(sr, si, cr[4],  cr[5],  (lane & 1) != 0);          // (4,5)
        cr_reg<BR, 0, 0x44>(sr, si, cr[6],  cr[7],  true);                     // (6,7)
        cr_lane<BR>(sr, si, cr[8],  cr[9],  2, ((lane >> 3) & 1) != 0, lane);  // (1,2)
        cr_lane<BR>(sr, si, cr[10], cr[11], 0, ((lane >> 1) & 1) != 0, lane);  // (3,4)
        cr_reg<BR, 1, 0x30>(sr, si, cr[12], cr[13], true);                     // (5,6)
    } else {
        ztab_apply(sr, si, zt0, lane);                                         // all 7 CRZ
    }

    u3_lane(sr, si, u3 + 0,  3, lane);     // u3[0] wire1
    u3_lane(sr, si, u3 + 8,  1, lane);     // u3[1] wire3
    u3_reg<2, 0x0F>(sr, si, u3 + 16);      // u3[2] wire5
    u3_reg<0, 0x55>(sr, si, u3 + 24);      // u3[3] wire7

    if (BR < 2) {
        cr_lane<BR>(sr, si, cr[14], cr[15], 1, ((lane >> 3) & 1) != 0, lane);  // (1,3)
        cr_reg<BR, 0, 0x50>(sr, si, cr[16], cr[17], true);                     // (5,7)
        cr_reg<BR, 2, 0x0F>(sr, si, cr[18], cr[19], ((lane >> 1) & 1) != 0);   // (3,5)
    } else {
        ztab_apply(sr, si, zt1, lane);                                         // 3 CRZ
    }

    u3_lane(sr, si, u3 + 32, 1, lane);     // u3[4] wire3
    u3_reg<0, 0x55>(sr, si, u3 + 40);      // u3[5] wire7

    // expval_z on qubit 3 (lane bit 1) and qubit 7 (reg bit 0)
    float e3 = 0.f, e7 = 0.f;
    float sgn3 = ((lane >> 1) & 1) ? -1.f : 1.f;
#pragma unroll
    for (int r = 0; r < 8; r++) {
        float p = fmaf(sr[r], sr[r], si[r] * si[r]);
        e3 = fmaf(sgn3, p, e3);
        e7 += (r & 1) ? -p : p;
    }
#pragma unroll
    for (int o = 16; o; o >>= 1) {
        e3 += __shfl_xor_sync(FULLMASK, e3, o);
        e7 += __shfl_xor_sync(FULLMASK, e7, o);
    }
    e3o = e3; e7o = e7;
}

__global__ __launch_bounds__(256) void qcnn_main(
    const float* __restrict__ x,
    const float* __restrict__ w1, const float* __restrict__ b1,
    const float* __restrict__ w2, const float* __restrict__ b2,
    float* __restrict__ out, int B) {
    __shared__ float  s_cr[60];
    __shared__ float  s_u3[144];
    __shared__ float2 s_zt[2][256];
    __shared__ float  sw1[72];
    __shared__ float  sb1[12];
    __shared__ float  sw2[12];
    __shared__ float  sb2;

    int t = threadIdx.x;
    if (t < 60) s_cr[t] = g_cr[t];
    if (t >= 64 && t < 208) s_u3[t - 64] = g_u3[t - 64];
    ((float4*)s_zt)[t] = ((const float4*)g_zt)[t];   // 256 x float4 = 512 float2
    if (t < 72) sw1[t] = w1[t];
    if (t >= 72 && t < 84)  sb1[t - 72] = b1[t - 72];
    if (t >= 84 && t < 96)  sw2[t - 84] = w2[t - 84];
    if (t == 96) sb2 = b2[0];
    __syncthreads();

    int warp = (blockIdx.x * blockDim.x + t) >> 5;
    if (warp >= B) return;
    int lane = t & 31;

    // ---- encode: product state from cos/sin(x/2) ----
    float xv = x[(warp << 3) + (lane & 7)];
    float ch = __cosf(0.5f * xv);
    float sh = __sinf(0.5f * xv);
    float c0 = __shfl_sync(FULLMASK, ch, 0), s0 = __shfl_sync(FULLMASK, sh, 0);
    float c1 = __shfl_sync(FULLMASK, ch, 1), s1 = __shfl_sync(FULLMASK, sh, 1);
    float c2 = __shfl_sync(FULLMASK, ch, 2), s2 = __shfl_sync(FULLMASK, sh, 2);
    float c3 = __shfl_sync(FULLMASK, ch, 3), s3 = __shfl_sync(FULLMASK, sh, 3);
    float c4 = __shfl_sync(FULLMASK, ch, 4), s4 = __shfl_sync(FULLMASK, sh, 4);
    float c5 = __shfl_sync(FULLMASK, ch, 5), s5 = __shfl_sync(FULLMASK, sh, 5);
    float c6 = __shfl_sync(FULLMASK, ch, 6), s6 = __shfl_sync(FULLMASK, sh, 6);
    float c7 = __shfl_sync(FULLMASK, ch, 7), s7 = __shfl_sync(FULLMASK, sh, 7);

    float L = (((lane >> 4) & 1) ? s0 : c0)
            * (((lane >> 3) & 1) ? s1 : c1)
            * (((lane >> 2) & 1) ? s2 : c2)
            * (((lane >> 1) & 1) ? s3 : c3)
            * ((lane & 1) ? s4 : c4);

    float init[8];
#pragma unroll
    for (int r = 0; r < 8; r++)
        init[r] = L * ((r & 4) ? s5 : c5) * ((r & 2) ? s6 : c6) * ((r & 1) ? s7 : c7);

    float f0, f1, f2, f3, f4, f5v;
    run_branch<0>(init, lane, s_cr +  0, s_u3 +  0, s_zt[0], s_zt[1], f0, f1);
    run_branch<1>(init, lane, s_cr + 20, s_u3 + 48, s_zt[0], s_zt[1], f2, f3);
    run_branch<2>(init, lane, s_cr + 40, s_u3 + 96, s_zt[0], s_zt[1], f4, f5v);

    // ---- MLP head: parallel over lanes 0..11 (one tanh latency) ----
    float contrib = 0.f;
    if (lane < 12) {
        float h = sb1[lane];
        h = fmaf(sw1[lane * 6 + 0], f0, h);
        h = fmaf(sw1[lane * 6 + 1], f1, h);
        h = fmaf(sw1[lane * 6 + 2], f2, h);
        h = fmaf(sw1[lane * 6 + 3], f3, h);
        h = fmaf(sw1[lane * 6 + 4], f4, h);
        h = fmaf(sw1[lane * 6 + 5], f5v, h);
        contrib = sw2[lane] * tanhf(h);
    }
#pragma unroll
    for (int o = 16; o; o >>= 1) contrib += __shfl_xor_sync(FULLMASK, contrib, o);
    if (lane == 0) out[warp] = 1.0f / (1.0f + expf(-(contrib + sb2)));
}

extern "C" void kernel_launch(void* const* d_in, const int* in_sizes, int n_in,
                              void* d_out, int out_size) {
    const float* x    = (const float*)d_in[0];
    const float* crx  = (const float*)d_in[1];
    const float* u3x  = (const float*)d_in[2];
    const float* cry  = (const float*)d_in[3];
    const float* u3y  = (const float*)d_in[4];
    const float* crz  = (const float*)d_in[5];
    const float* u3z  = (const float*)d_in[6];
    const float* w1   = (const float*)d_in[7];
    const float* b1   = (const float*)d_in[8];
    const float* w2   = (const float*)d_in[9];
    const float* b2   = (const float*)d_in[10];
    float* out = (float*)d_out;

    int B = in_sizes[0] / NQ;   // 32768

    prep_gates<<<1, 256>>>(crx, u3x, cry, u3y, crz, u3z);

    int threads = 256;
    int blocks = (B + (threads / 32) - 1) / (threads / 32);
    qcnn_main<<<blocks, threads>>>(x, w1, b1, w2, b2, out, B);
}

// round 4
// speedup vs baseline: 1.6950x; 1.0795x over previous
#include <cuda_runtime.h>
#include <cuda_bf16.h>

// One warp per batch element. 8-qubit state (256 complex amps) in registers.
// NEW layout: lane bits (4..0) = qubits {0,1,2,4,6}; reg bits (2..0) = qubits
// {3,5,7} (the hot gate targets + both measured qubits). Lane-target gates
// need SHFLs; reg-target gates are pure register math.
// Fusions: [u3[1]; CR(1,3)] -> one reg gate (lane-bit3-selected matrix);
// [u3[3]; CR(5,7); u3[5]] -> one reg gate (per-pair reg-bit1-selected matrix).
// CRZ layers collapse to precomputed per-amplitude phase tables.

#define NQ 8
#define FULLMASK 0xffffffffu

__device__ float  g_cr[60];        // [br][10][{c,s}]  (only 0..6 and 9 used directly)
__device__ float  g_u3[144];       // [br][6][8]
__device__ float  g_m3[48];        // [br][2][8]  fused wire3 (X/Y): {u3[1], R7*u3[1]}
__device__ float  g_m7[48];        // [br][2][8]  fused wire7: {u5*u3, u5*R8*u3}
__device__ float2 g_zt[2][256];    // [layer][r*32+lane] phase table (Z branch)

// C = A * B (2x2 complex, layout r,i interleaved row-major)
__device__ __forceinline__ void cmm(const float* A, const float* Bm, float* C) {
#pragma unroll
    for (int i = 0; i < 2; i++)
#pragma unroll
        for (int j = 0; j < 2; j++) {
            float ar0 = A[i*4+0], ai0 = A[i*4+1], ar1 = A[i*4+2], ai1 = A[i*4+3];
            float br0 = Bm[j*2], bi0 = Bm[j*2+1], br1 = Bm[4+j*2], bi1 = Bm[4+j*2+1];
            C[i*4+j*2]   = ar0*br0 - ai0*bi0 + ar1*br1 - ai1*bi1;
            C[i*4+j*2+1] = ar0*bi0 + ai0*br0 + ar1*bi1 + ai1*br1;
        }
}

__device__ __forceinline__ void build_rot(int br, float theta, float* R) {
    float c = cosf(0.5f * theta), s = sinf(0.5f * theta);
    if (br == 0)      { R[0]=c; R[1]=0;  R[2]=0;  R[3]=-s; R[4]=0; R[5]=-s; R[6]=c; R[7]=0; }
    else if (br == 1) { R[0]=c; R[1]=0;  R[2]=-s; R[3]=0;  R[4]=s; R[5]=0;  R[6]=c; R[7]=0; }
    else              { R[0]=c; R[1]=-s; R[2]=0;  R[3]=0;  R[4]=0; R[5]=0;  R[6]=c; R[7]=s; }
}

__global__ void prep_gates(const float* __restrict__ crx, const float* __restrict__ u3x,
                           const float* __restrict__ cry, const float* __restrict__ u3y,
                           const float* __restrict__ crz, const float* __restrict__ u3z) {
    int t = threadIdx.x;
    if (t < 3) {
        int br = t;
        const float* crp = (br == 0) ? crx : (br == 1) ? cry : crz;
        const float* u3p = (br == 0) ? u3x : (br == 1) ? u3y : u3z;
        float u[6][8];
#pragma unroll
        for (int k = 0; k < 6; k++) {
            float th = u3p[3*k], ph = u3p[3*k+1], lm = u3p[3*k+2];
            float ct = cosf(0.5f*th), st = sinf(0.5f*th);
            float cp = cosf(ph), sp = sinf(ph);
            float cl = cosf(lm), sl = sinf(lm);
            u[k][0] = ct;       u[k][1] = 0.f;
            u[k][2] = -cl*st;   u[k][3] = -sl*st;
            u[k][4] = cp*st;    u[k][5] = sp*st;
            u[k][6] = (cp*cl - sp*sl)*ct;
            u[k][7] = (sp*cl + cp*sl)*ct;
#pragma unroll
            for (int j = 0; j < 8; j++) g_u3[br*48 + k*8 + j] = u[k][j];
        }
#pragma unroll
        for (int g = 0; g < 10; g++) {
            float th = 0.5f * crp[g];
            g_cr[(br*10 + g)*2 + 0] = cosf(th);
            g_cr[(br*10 + g)*2 + 1] = sinf(th);
        }
        float R7[8], R8[8], tmp[8];
        build_rot(br, crp[7], R7);
        build_rot(br, crp[8], R8);
        // m3: fused wire3 = CR(1,3)-part * u3[1]
#pragma unroll
        for (int j = 0; j < 8; j++) g_m3[br*16 + j] = u[1][j];
        cmm(R7, u[1], &g_m3[br*16 + 8]);
        // m7: fused wire7 = u3[5] * CR(5,7)-part * u3[3]
        cmm(u[5], u[3], &g_m7[br*16]);
        cmm(R8, u[3], tmp);
        cmm(u[5], tmp, &g_m7[br*16 + 8]);
    }
    // CRZ phase tables (new layout): lane bits 4..0 = q0,q1,q2,q4,q6; reg = q3,q5,q7
    {
        int lane = t & 31, r = t >> 5;
        int q0 = (lane>>4)&1, q1 = (lane>>3)&1, q2 = (lane>>2)&1;
        int q4 = (lane>>1)&1, q6 = lane&1;
        int q3 = (r>>2)&1, q5 = (r>>1)&1, q7 = r&1;
        int qv[8] = {q0,q1,q2,q3,q4,q5,q6,q7};
        const int c1[7] = {0,2,4,6,1,3,5};
        const int t1[7] = {1,3,5,7,2,4,6};
        float p1 = 0.f;
#pragma unroll
        for (int i = 0; i < 7; i++)
            if (qv[c1[i]]) p1 += qv[t1[i]] ? 0.5f*crz[i] : -0.5f*crz[i];
        // layer2': only (1,3)->crz[7] and (3,5)->crz[9]  ((5,7) folded into m7)
        float p2 = 0.f;
        if (qv[1]) p2 += qv[3] ? 0.5f*crz[7] : -0.5f*crz[7];
        if (qv[3]) p2 += qv[5] ? 0.5f*crz[9] : -0.5f*crz[9];
        int idx = r*32 + lane;
        g_zt[0][idx] = make_float2(cosf(p1), sinf(p1));
        g_zt[1][idx] = make_float2(cosf(p2), sinf(p2));
    }
}

// ---- lane-target CR gate. RMASK: which registers participate (reg-resident
// control => compile-time mask, half the shfls). act: lane-resident control.
template <int BR, unsigned RMASK>
__device__ __forceinline__ void cr_lane(float (&sr)[8], float (&si)[8],
                                        float c, float s, int tbit, bool act, int lane) {
    const unsigned m = 1u << tbit;
    float coef = s;
    if (BR == 1) coef = ((lane >> tbit) & 1) ? s : -s;
#pragma unroll
    for (int r = 0; r < 8; r++) {
        if (!((RMASK >> r) & 1)) continue;
        float pr = __shfl_xor_sync(FULLMASK, sr[r], m);
        float pi = __shfl_xor_sync(FULLMASK, si[r], m);
        float nr, ni;
        if (BR == 0) { nr = fmaf(coef, pi, c * sr[r]); ni = fmaf(-coef, pr, c * si[r]); }
        else         { nr = fmaf(coef, pr, c * sr[r]); ni = fmaf(coef, pi, c * si[r]); }
        if (act) { sr[r] = nr; si[r] = ni; }
    }
}

// ---- reg-target CR gate. TB: target reg bit. MASK: active low-pair r0 set.
template <int BR, int TB, unsigned MASK>
__device__ __forceinline__ void cr_reg(float (&sr)[8], float (&si)[8],
                                       float c, float s, bool act) {
#pragma unroll
    for (int r0 = 0; r0 < 8; r0++) {
        if (r0 & (1 << TB)) continue;
        if (!((MASK >> r0) & 1)) continue;
        const int r1 = r0 | (1 << TB);
        float ar = sr[r0], ai = si[r0];
        float br_ = sr[r1], bi = si[r1];
        float n0r, n0i, n1r, n1i;
        if (BR == 0) {
            n0r = fmaf(s, bi, c * ar);   n0i = fmaf(-s, br_, c * ai);
            n1r = fmaf(s, ai, c * br_);  n1i = fmaf(-s, ar, c * bi);
        } else {
            n0r = fmaf(-s, br_, c * ar); n0i = fmaf(-s, bi, c * ai);
            n1r = fmaf(s, ar, c * br_);  n1i = fmaf(s, ai, c * bi);
        }
        if (act) { sr[r0] = n0r; si[r0] = n0i; sr[r1] = n1r; si[r1] = n1i; }
    }
}

// CRZ layer: per-amplitude phase multiply from smem table
__device__ __forceinline__ void ztab_apply(float (&sr)[8], float (&si)[8],
                                           const float2* __restrict__ tab, int lane) {
#pragma unroll
    for (int r = 0; r < 8; r++) {
        float2 p = tab[r * 32 + lane];
        float nr = fmaf(-p.y, si[r], p.x * sr[r]);
        float ni = fmaf(p.y, sr[r], p.x * si[r]);
        sr[r] = nr; si[r] = ni;
    }
}

// ---- generic lane-target u3 gate (unconditional, full)
__device__ __forceinline__ void u3_lane(float (&sr)[8], float (&si)[8],
                                        const float* __restrict__ g, int tbit, int lane) {
    const unsigned m = 1u << tbit;
    const int bit = (lane >> tbit) & 1;
    const float cmr = bit ? g[6] : g[0];
    const float cmi = bit ? g[7] : g[1];
    const float cpr = bit ? g[4] : g[2];
    const float cpi = bit ? g[5] : g[3];
#pragma unroll
    for (int r = 0; r < 8; r++) {
        float pr = __shfl_xor_sync(FULLMASK, sr[r], m);
        float pi = __shfl_xor_sync(FULLMASK, si[r], m);
        float nr = cmr * sr[r] - cmi * si[r] + cpr * pr - cpi * pi;
        float ni = cmr * si[r] + cmi * sr[r] + cpr * pi + cpi * pr;
        sr[r] = nr; si[r] = ni;
    }
}

// ---- reg-target u3 gate
template <int TB, unsigned MASK>
__device__ __forceinline__ void u3_reg(float (&sr)[8], float (&si)[8],
                                       const float* __restrict__ g) {
    const float u00r = g[0], u00i = g[1], u01r = g[2], u01i = g[3];
    const float u10r = g[4], u10i = g[5], u11r = g[6], u11i = g[7];
#pragma unroll
    for (int r0 = 0; r0 < 8; r0++) {
        if (r0 & (1 << TB)) continue;
        if (!((MASK >> r0) & 1)) continue;
        const int r1 = r0 | (1 << TB);
        float ar = sr[r0], ai = si[r0];
        float br_ = sr[r1], bi = si[r1];
        sr[r0] = u00r * ar - u00i * ai + u01r * br_ - u01i * bi;
        si[r0] = u00r * ai + u00i * ar + u01r * bi + u01i * br_;
        sr[r1] = u10r * ar - u10i * ai + u11r * br_ - u11i * bi;
        si[r1] = u10r * ai + u10i * ar + u11r * bi + u11i * br_;
    }
}

// ---- reg-target u3 gate, matrix selected per pair by reg bit SELBIT
template <int TB, unsigned MASK, int SELBIT>
__device__ __forceinline__ void u3_reg2(float (&sr)[8], float (&si)[8],
                                        const float* __restrict__ ga,
                                        const float* __restrict__ gb) {
#pragma unroll
    for (int r0 = 0; r0 < 8; r0++) {
        if (r0 & (1 << TB)) continue;
        if (!((MASK >> r0) & 1)) continue;
        const float* g = ((r0 >> SELBIT) & 1) ? gb : ga;   // compile-time
        const int r1 = r0 | (1 << TB);
        float ar = sr[r0], ai = si[r0];
        float br_ = sr[r1], bi = si[r1];
        sr[r0] = g[0]*ar - g[1]*ai + g[2]*br_ - g[3]*bi;
        si[r0] = g[0]*ai + g[1]*ar + g[2]*bi + g[3]*br_;
        sr[r1] = g[4]*ar - g[5]*ai + g[6]*br_ - g[7]*bi;
        si[r1] = g[4]*ai + g[5]*ar + g[6]*bi + g[7]*br_;
    }
}

template <int BR>
__device__ __forceinline__ void run_branch(const float (&init)[8], int lane,
                                           const float* __restrict__ cr,    // [10][2]
                                           const float* __restrict__ u3,    // [6][8]
                                           const float* __restrict__ m3,    // [2][8]
                                           const float* __restrict__ m7,    // [2][8]
                                           const float2* __restrict__ zt0,
                                           const float2* __restrict__ zt1,
                                           float& e3o, float& e7o) {
    float sr[8], si[8];
#pragma unroll
    for (int r = 0; r < 8; r++) { sr[r] = init[r]; si[r] = 0.f; }

    if (BR < 2) {
        // CR_PAIRS_1: (0,1),(2,3),(4,5),(6,7),(1,2),(3,4),(5,6)
        cr_lane<BR, 0xFF>(sr, si, cr[0],  cr[1],  3, ((lane >> 4) & 1) != 0, lane); // (0,1)
        cr_reg<BR, 2, 0x0F>(sr, si, cr[2],  cr[3],  ((lane >> 2) & 1) != 0);        // (2,3)
        cr_reg<BR, 1, 0x33>(sr, si, cr[4],  cr[5],  ((lane >> 1) & 1) != 0);        // (4,5)
        cr_reg<BR, 0, 0x55>(sr, si, cr[6],  cr[7],  (lane & 1) != 0);               // (6,7)
        cr_lane<BR, 0xFF>(sr, si, cr[8],  cr[9],  2, ((lane >> 3) & 1) != 0, lane); // (1,2)
        cr_lane<BR, 0xF0>(sr, si, cr[10], cr[11], 1, true, lane);                   // (3,4) ctrl q3=reg bit2
        cr_lane<BR, 0xCC>(sr, si, cr[12], cr[13], 0, true, lane);                   // (5,6) ctrl q5=reg bit1
    } else {
        ztab_apply(sr, si, zt0, lane);                                              // all 7 CRZ
    }

    u3_lane(sr, si, u3 + 0, 3, lane);                  // u3[0] wire1 (lane bit3)

    if (BR < 2) {
        // fused wire3: [u3[1]; CR(1,3)], matrix selected by lane bit3 (q1 ctrl)
        float m[8];
        const bool b3 = ((lane >> 3) & 1) != 0;
#pragma unroll
        for (int k = 0; k < 8; k++) m[k] = b3 ? m3[8 + k] : m3[k];
        u3_reg<2, 0x0F>(sr, si, m);
    } else {
        u3_reg<2, 0x0F>(sr, si, u3 + 8);               // u3[1] wire3 (plain for Z)
    }

    u3_reg<1, 0x33>(sr, si, u3 + 16);                  // u3[2] wire5
    u3_reg2<0, 0x55, 1>(sr, si, m7, m7 + 8);           // fused wire7: [u3[3]; CR(5,7); u3[5]]

    if (BR < 2) {
        cr_reg<BR, 1, 0x30>(sr, si, cr[18], cr[19], true);  // (3,5) ctrl reg bit2
    } else {
        ztab_apply(sr, si, zt1, lane);                      // (1,3)+(3,5) phases
    }

    u3_reg<2, 0x0F>(sr, si, u3 + 32);                  // u3[4] wire3

    // expval_z: qubit 3 = reg bit2, qubit 7 = reg bit0 (compile-time signs)
    float e3 = 0.f, e7 = 0.f;
#pragma unroll
    for (int r = 0; r < 8; r++) {
        float p = fmaf(sr[r], sr[r], si[r] * si[r]);
        e3 += (r & 4) ? -p : p;
        e7 += (r & 1) ? -p : p;
    }
#pragma unroll
    for (int o = 16; o; o >>= 1) {
        e3 += __shfl_xor_sync(FULLMASK, e3, o);
        e7 += __shfl_xor_sync(FULLMASK, e7, o);
    }
    e3o = e3; e7o = e7;
}

__global__ __launch_bounds__(256) void qcnn_main(
    const float* __restrict__ x,
    const float* __restrict__ w1, const float* __restrict__ b1,
    const float* __restrict__ w2, const float* __restrict__ b2,
    float* __restrict__ out, int B) {
    __shared__ float  s_cr[60];
    __shared__ float  s_u3[144];
    __shared__ float  s_m3[48];
    __shared__ float  s_m7[48];
    __shared__ float2 s_zt[2][256];
    __shared__ float  sw1[72];
    __shared__ float  sb1[12];
    __shared__ float  sw2[12];
    __shared__ float  sb2;

    int t = threadIdx.x;
    if (t < 60)  s_cr[t] = g_cr[t];
    if (t < 144) s_u3[t] = g_u3[t];
    if (t < 48)  { s_m3[t] = g_m3[t]; s_m7[t] = g_m7[t]; }
    ((float4*)s_zt)[t] = ((const float4*)g_zt)[t];    // 256 * float4 = 512 float2
    if (t < 72) sw1[t] = w1[t];
    if (t < 12) { sb1[t] = b1[t]; sw2[t] = w2[t]; }
    if (t == 0) sb2 = b2[0];
    __syncthreads();

    int warp = (blockIdx.x * blockDim.x + t) >> 5;
    if (warp >= B) return;
    int lane = t & 31;

    // ---- encode ----
    float xv = x[(warp << 3) + (lane & 7)];
    float ch = __cosf(0.5f * xv);
    float sh = __sinf(0.5f * xv);
    float c0 = __shfl_sync(FULLMASK, ch, 0), s0 = __shfl_sync(FULLMASK, sh, 0);
    float c1 = __shfl_sync(FULLMASK, ch, 1), s1 = __shfl_sync(FULLMASK, sh, 1);
    float c2 = __shfl_sync(FULLMASK, ch, 2), s2 = __shfl_sync(FULLMASK, sh, 2);
    float c3 = __shfl_sync(FULLMASK, ch, 3), s3 = __shfl_sync(FULLMASK, sh, 3);
    float c4 = __shfl_sync(FULLMASK, ch, 4), s4 = __shfl_sync(FULLMASK, sh, 4);
    float c5 = __shfl_sync(FULLMASK, ch, 5), s5 = __shfl_sync(FULLMASK, sh, 5);
    float c6 = __shfl_sync(FULLMASK, ch, 6), s6 = __shfl_sync(FULLMASK, sh, 6);
    float c7 = __shfl_sync(FULLMASK, ch, 7), s7 = __shfl_sync(FULLMASK, sh, 7);

    // lane bits 4..0 = q0,q1,q2,q4,q6 ; reg bits 2..0 = q3,q5,q7
    float L = (((lane >> 4) & 1) ? s0 : c0)
            * (((lane >> 3) & 1) ? s1 : c1)
            * (((lane >> 2) & 1) ? s2 : c2)
            * (((lane >> 1) & 1) ? s4 : c4)
            * ((lane & 1) ? s6 : c6);

    float init[8];
#pragma unroll
    for (int r = 0; r < 8; r++)
        init[r] = L * ((r & 4) ? s3 : c3) * ((r & 2) ? s5 : c5) * ((r & 1) ? s7 : c7);

    float f0, f1, f2, f3, f4, f5v;
    run_branch<0>(init, lane, s_cr +  0, s_u3 +  0, s_m3 +  0, s_m7 +  0, s_zt[0], s_zt[1], f0, f1);
    run_branch<1>(init, lane, s_cr + 20, s_u3 + 48, s_m3 + 16, s_m7 + 16, s_zt[0], s_zt[1], f2, f3);
    run_branch<2>(init, lane, s_cr + 40, s_u3 + 96, s_m3 + 32, s_m7 + 32, s_zt[0], s_zt[1], f4, f5v);

    // ---- MLP head: parallel over lanes 0..11 ----
    float contrib = 0.f;
    if (lane < 12) {
        float h = sb1[lane];
        h = fmaf(sw1[lane * 6 + 0], f0, h);
        h = fmaf(sw1[lane * 6 + 1], f1, h);
        h = fmaf(sw1[lane * 6 + 2], f2, h);
        h = fmaf(sw1[lane * 6 + 3], f3, h);
        h = fmaf(sw1[lane * 6 + 4], f4, h);
        h = fmaf(sw1[lane * 6 + 5], f5v, h);
        contrib = sw2[lane] * tanhf(h);
    }
#pragma unroll
    for (int o = 16; o; o >>= 1) contrib += __shfl_xor_sync(FULLMASK, contrib, o);
    if (lane == 0) out[warp] = 1.0f / (1.0f + expf(-(contrib + sb2)));
}

extern "C" void kernel_launch(void* const* d_in, const int* in_sizes, int n_in,
                              void* d_out, int out_size) {
    const float* x    = (const float*)d_in[0];
    const float* crx  = (const float*)d_in[1];
    const float* u3x  = (const float*)d_in[2];
    const float* cry  = (const float*)d_in[3];
    const float* u3y  = (const float*)d_in[4];
    const float* crz  = (const float*)d_in[5];
    const float* u3z  = (const float*)d_in[6];
    const float* w1   = (const float*)d_in[7];
    const float* b1   = (const float*)d_in[8];
    const float* w2   = (const float*)d_in[9];
    const float* b2   = (const float*)d_in[10];
    float* out = (float*)d_out;

    int B = in_sizes[0] / NQ;   // 32768

    prep_gates<<<1, 256>>>(crx, u3x, cry, u3y, crz, u3z);

    int threads = 256;
    int blocks = (B + (threads / 32) - 1) / (threads / 32);
    qcnn_main<<<blocks, threads>>>(x, w1, b1, w2, b2, out, B);
}